// round 10
// baseline (speedup 1.0000x reference)
#include <cuda_runtime.h>
#include <cuda_fp16.h>
#include <math.h>
#include <stdint.h>

// ---------------------------------------------------------------------------
// Fused transformer block: B=2048, N=15, C=1024, H=16, HS=64
// Round 9: fp16 HMMA 128x128 CTA / 64x32 warp tile, k32 4-stage cp.async
//          (prefetch distance 3), one __syncthreads per stage, 2 CTAs/SM.
//          W_Iconv folded into Iqk weight (N 3072->2304).
// ---------------------------------------------------------------------------

#define M_ROWS 30720
using f16 = __half;

__device__ f16   g_xj[(size_t)M_ROWS * 1024];
__device__ f16   g_xi[(size_t)M_ROWS * 1024];
__device__ f16   g_Jqkv[(size_t)M_ROWS * 3072];
__device__ f16   g_Iqk[(size_t)M_ROWS * 2304];
__device__ f16   g_attno[(size_t)M_ROWS * 1024];
__device__ f16   g_ln2[(size_t)M_ROWS * 1024];
__device__ f16   g_hid[(size_t)M_ROWS * 512];
__device__ float g_joint[(size_t)M_ROWS * 1024];
__device__ float g_wlin[1024 * 240];
// fp16 weights (native [K,N])
__device__ f16 g_wJ[1024 * 3072];
__device__ f16 g_wI[1024 * 2304];
__device__ f16 g_wP[1024 * 1024];
__device__ f16 g_w1[1024 * 512];
__device__ f16 g_w2[512 * 1024];

// ---------------------------------------------------------------------------
__device__ __forceinline__ uint32_t smem_u32(const void* p) {
    uint32_t a;
    asm("{ .reg .u64 t; cvta.to.shared.u64 t, %1; cvt.u32.u64 %0, t; }"
        : "=r"(a) : "l"(p));
    return a;
}
__device__ __forceinline__ void cp16s(uint32_t saddr, const void* g) {
    asm volatile("cp.async.cg.shared.global [%0], [%1], 16;\n" ::"r"(saddr),
                 "l"(g));
}
__device__ __forceinline__ void cp_commit() {
    asm volatile("cp.async.commit_group;\n");
}
template <int NN>
__device__ __forceinline__ void cp_wait() {
    asm volatile("cp.async.wait_group %0;\n" ::"n"(NN));
}
__device__ __forceinline__ float gelu_exact(float x) {
    return 0.5f * x * (1.0f + erff(x * 0.70710678118654752f));
}

// ---------------------------------------------------------------------------
// W_lin[c][h*15+j] = sum_d W_Iqk[c][2048+h*64+d] * W_Iconv[d][j]
// ---------------------------------------------------------------------------
__global__ __launch_bounds__(256) void wlin_kernel(
    const float* __restrict__ W_Iqk, const float* __restrict__ W_Iconv,
    float* __restrict__ out) {
    int idx = blockIdx.x * 256 + threadIdx.x;  // 1024*240
    int c = idx / 240, r = idx % 240;
    int h = r / 15, j = r % 15;
    const float* wv = W_Iqk + (size_t)c * 3072 + 2048 + h * 64;
    float s = 0.f;
#pragma unroll 8
    for (int d = 0; d < 64; d++) s += wv[d] * W_Iconv[d * 15 + j];
    out[idx] = s;
}

// pack Iqk weight: cols [0,2048) from W_Iqk, [2048,2288) = wlin, pad 0
__global__ __launch_bounds__(256) void pack_wI_kernel(
    const float* __restrict__ W_Iqk, const float* __restrict__ wlin,
    f16* __restrict__ out) {
    int idx = blockIdx.x * 256 + threadIdx.x;  // 1024*2304
    int k = idx / 2304, n = idx % 2304;
    float v = (n < 2048) ? W_Iqk[(size_t)k * 3072 + n]
                         : ((n < 2288) ? wlin[k * 240 + (n - 2048)] : 0.f);
    out[idx] = __float2half(v);
}

__global__ __launch_bounds__(256) void f2h_kernel(const float* __restrict__ in,
                                                  f16* __restrict__ out, int n) {
    int i = (blockIdx.x * 256 + threadIdx.x) * 4;
    if (i < n) {
        float4 v = *reinterpret_cast<const float4*>(in + i);
        *reinterpret_cast<__half2*>(out + i) = __floats2half2_rn(v.x, v.y);
        *reinterpret_cast<__half2*>(out + i + 2) = __floats2half2_rn(v.z, v.w);
    }
}

// ---------------------------------------------------------------------------
// LayerNorm (fp32 in, fp16 out)
// ---------------------------------------------------------------------------
__global__ __launch_bounds__(256) void ln_kernel(
    const float* __restrict__ x, const float* __restrict__ g,
    const float* __restrict__ b, f16* __restrict__ out) {
    int row = blockIdx.x;
    const float4* xr = reinterpret_cast<const float4*>(x + (size_t)row * 1024);
    float4 v = xr[threadIdx.x];
    float s = v.x + v.y + v.z + v.w;
    float sq = v.x * v.x + v.y * v.y + v.z * v.z + v.w * v.w;
#pragma unroll
    for (int o = 16; o > 0; o >>= 1) {
        s += __shfl_xor_sync(0xffffffffu, s, o);
        sq += __shfl_xor_sync(0xffffffffu, sq, o);
    }
    __shared__ float ss[8], ssq[8];
    int w = threadIdx.x >> 5;
    if ((threadIdx.x & 31) == 0) { ss[w] = s; ssq[w] = sq; }
    __syncthreads();
    float ts = 0.f, tq = 0.f;
#pragma unroll
    for (int i = 0; i < 8; i++) { ts += ss[i]; tq += ssq[i]; }
    float mean = ts * (1.0f / 1024.0f);
    float var = tq * (1.0f / 1024.0f) - mean * mean;
    float rstd = rsqrtf(var + 1e-5f);
    int c = threadIdx.x * 4;
    float4 gg = *reinterpret_cast<const float4*>(g + c);
    float4 bb = *reinterpret_cast<const float4*>(b + c);
    float o0 = (v.x - mean) * rstd * gg.x + bb.x;
    float o1 = (v.y - mean) * rstd * gg.y + bb.y;
    float o2 = (v.z - mean) * rstd * gg.z + bb.z;
    float o3 = (v.w - mean) * rstd * gg.w + bb.w;
    f16* orow = out + (size_t)row * 1024 + c;
    *reinterpret_cast<__half2*>(orow) = __floats2half2_rn(o0, o1);
    *reinterpret_cast<__half2*>(orow + 2) = __floats2half2_rn(o2, o3);
}

// ---------------------------------------------------------------------------
// fp16 HMMA GEMM: C[M,N] = A[M,K] @ B[K,N] (+epilogue)
// CTA 128x128x32-per-stage, 8 warps (2x4), warp 64x32 m16n8k16.
// 4-stage cp.async, prefetch distance 3, one __syncthreads per stage.
// Stage: A 128x80B (10240) + B 32x272B (8704) = 18944; 4 stages = 75776 B.
// EPI: 0 = fp16 out; 1 = +bias+residual fp32 out; 2 = +bias, GELU, fp16 out
// ---------------------------------------------------------------------------
#define AST 10240
#define STG_B 18944
#define GSMEM_BYTES (4 * STG_B)

template <int KT, int EPI, typename OT>
__global__ __launch_bounds__(256, 2) void gemm_hmma(
    const f16* __restrict__ A, const f16* __restrict__ Bw,
    const float* __restrict__ bias, const float* __restrict__ res,
    OT* __restrict__ Cout, int N) {
    extern __shared__ __align__(128) char smem[];
    const int K = KT * 32;
    uint32_t sb = smem_u32(smem);
    int tid = threadIdx.x, lane = tid & 31, wid = tid >> 5;
    int bm = blockIdx.y * 128, bn = blockIdx.x * 128;
    int wm = (wid >> 2) * 64, wn = (wid & 3) * 32;
    int g = lane >> 2, tg = lane & 3;

    float acc[4][4][4];
#pragma unroll
    for (int a = 0; a < 4; a++)
#pragma unroll
        for (int b2 = 0; b2 < 4; b2++)
#pragma unroll
            for (int c = 0; c < 4; c++) acc[a][b2][c] = 0.f;

    auto load_stage = [&](int s, int t) {
        uint32_t ab = sb + s * STG_B;
        uint32_t bb2 = ab + AST;
#pragma unroll
        for (int i = 0; i < 2; i++) {
            int c = tid + i * 256;
            int r = c >> 2, ch = c & 3;
            cp16s(ab + r * 80 + ch * 16,
                  A + (size_t)(bm + r) * K + t * 32 + ch * 8);
        }
#pragma unroll
        for (int i = 0; i < 2; i++) {
            int c = tid + i * 256;
            int r = c >> 4, ch = c & 15;
            cp16s(bb2 + r * 272 + ch * 16,
                  Bw + (size_t)(t * 32 + r) * N + bn + ch * 8);
        }
    };

    load_stage(0, 0); cp_commit();
    load_stage(1, 1); cp_commit();
    load_stage(2, 2); cp_commit();

#pragma unroll 1
    for (int t = 0; t < KT; ++t) {
        cp_wait<2>();
        __syncthreads();
        if (t + 3 < KT) load_stage((t + 3) & 3, t + 3);
        cp_commit();
        uint32_t ab = sb + (t & 3) * STG_B;
        uint32_t bb2 = ab + AST;
#pragma unroll
        for (int kk = 0; kk < 32; kk += 16) {
            unsigned af[4][4], bfr[2][4];
#pragma unroll
            for (int mt = 0; mt < 4; mt++) {
                uint32_t addr = ab + (wm + mt * 16 + (lane & 15)) * 80 +
                                (kk + (lane >> 4) * 8) * 2;
                asm volatile(
                    "ldmatrix.sync.aligned.m8n8.x4.shared.b16 {%0,%1,%2,%3},[%4];"
                    : "=r"(af[mt][0]), "=r"(af[mt][1]), "=r"(af[mt][2]),
                      "=r"(af[mt][3])
                    : "r"(addr));
            }
#pragma unroll
            for (int hh = 0; hh < 2; hh++) {
                uint32_t addr = bb2 + (kk + (lane & 15)) * 272 +
                                (wn + hh * 16 + (lane >> 4) * 8) * 2;
                asm volatile(
                    "ldmatrix.sync.aligned.m8n8.x4.trans.shared.b16 "
                    "{%0,%1,%2,%3},[%4];"
                    : "=r"(bfr[hh][0]), "=r"(bfr[hh][1]), "=r"(bfr[hh][2]),
                      "=r"(bfr[hh][3])
                    : "r"(addr));
            }
#pragma unroll
            for (int mt = 0; mt < 4; mt++)
#pragma unroll
                for (int nt = 0; nt < 4; nt++) {
                    unsigned b0 = bfr[nt >> 1][(nt & 1) * 2];
                    unsigned b1 = bfr[nt >> 1][(nt & 1) * 2 + 1];
                    asm volatile(
                        "mma.sync.aligned.m16n8k16.row.col.f32.f16.f16.f32 "
                        "{%0,%1,%2,%3},{%4,%5,%6,%7},{%8,%9},{%0,%1,%2,%3};"
                        : "+f"(acc[mt][nt][0]), "+f"(acc[mt][nt][1]),
                          "+f"(acc[mt][nt][2]), "+f"(acc[mt][nt][3])
                        : "r"(af[mt][0]), "r"(af[mt][1]), "r"(af[mt][2]),
                          "r"(af[mt][3]), "r"(b0), "r"(b1));
                }
        }
    }

    // epilogue
#pragma unroll
    for (int mt = 0; mt < 4; mt++) {
        int row = bm + wm + mt * 16 + g;
#pragma unroll
        for (int nt = 0; nt < 4; nt++) {
            int col = bn + wn + nt * 8 + 2 * tg;
            size_t i0 = (size_t)row * N + col;
            size_t i1 = i0 + (size_t)8 * N;
            float c0 = acc[mt][nt][0], c1 = acc[mt][nt][1];
            float c2 = acc[mt][nt][2], c3 = acc[mt][nt][3];
            if (EPI == 1) {
                float2 bb = *reinterpret_cast<const float2*>(bias + col);
                float2 r0 = *reinterpret_cast<const float2*>(res + i0);
                float2 r1 = *reinterpret_cast<const float2*>(res + i1);
                c0 += bb.x + r0.x; c1 += bb.y + r0.y;
                c2 += bb.x + r1.x; c3 += bb.y + r1.y;
            } else if (EPI == 2) {
                float2 bb = *reinterpret_cast<const float2*>(bias + col);
                c0 = gelu_exact(c0 + bb.x); c1 = gelu_exact(c1 + bb.y);
                c2 = gelu_exact(c2 + bb.x); c3 = gelu_exact(c3 + bb.y);
            }
            if (sizeof(OT) == 4) {
                *reinterpret_cast<float2*>((float*)Cout + i0) = make_float2(c0, c1);
                *reinterpret_cast<float2*>((float*)Cout + i1) = make_float2(c2, c3);
            } else {
                *reinterpret_cast<__half2*>((f16*)Cout + i0) =
                    __floats2half2_rn(c0, c1);
                *reinterpret_cast<__half2*>((f16*)Cout + i1) =
                    __floats2half2_rn(c2, c3);
            }
        }
    }
}

// ---------------------------------------------------------------------------
// Attention: block per (b,h). logits = (JqJk + IqIk + lin)*0.125; out = P@Jv
// Jqkv [M,3072]; Iqk [M,2304] (q 0..1023, k 1024..2047, lin 2048+h*15+j)
// ---------------------------------------------------------------------------
__global__ __launch_bounds__(256) void attn_kernel(
    const f16* __restrict__ Jqkv, const f16* __restrict__ Iqk,
    f16* __restrict__ out) {
    int b = blockIdx.x, h = blockIdx.y;
    __shared__ float sm[5][15][64];  // Jq Jk Jv Iq Ik
    __shared__ float slin[15][15];
    __shared__ float slog[15][16];
    int tid = threadIdx.x;
    size_t baseJ = ((size_t)b * 15) * 3072 + h * 64;
    size_t baseI = ((size_t)b * 15) * 2304 + h * 64;

    for (int idx = tid; idx < 600; idx += 256) {
        int mat = idx / 120;
        int rem = idx % 120;
        int n = rem >> 3;
        int c8 = rem & 7;
        const f16* src;
        if (mat < 3) src = Jqkv + baseJ + (size_t)n * 3072 + mat * 1024;
        else         src = Iqk + baseI + (size_t)n * 2304 + (mat - 3) * 1024;
        const __half2* p = reinterpret_cast<const __half2*>(src + c8 * 8);
        float* d = &sm[mat][n][c8 * 8];
#pragma unroll
        for (int j = 0; j < 4; j++) {
            float2 f = __half22float2(p[j]);
            d[2 * j] = f.x;
            d[2 * j + 1] = f.y;
        }
    }
    if (tid < 225) {
        int q = tid / 15, k = tid % 15;
        slin[q][k] = __half2float(
            Iqk[((size_t)b * 15 + q) * 2304 + 2048 + h * 15 + k]);
    }
    __syncthreads();

    if (tid < 225) {
        int q = tid / 15, k = tid % 15;
        float s = slin[q][k];
#pragma unroll 8
        for (int d = 0; d < 64; d++) {
            s += sm[0][q][d] * sm[1][k][d];
            s += sm[3][q][d] * sm[4][k][d];
        }
        slog[q][k] = s * 0.125f;
    }
    __syncthreads();
    if (tid < 15) {
        int q = tid;
        float mx = -1e30f;
#pragma unroll
        for (int k = 0; k < 15; k++) mx = fmaxf(mx, slog[q][k]);
        float sum = 0.f;
#pragma unroll
        for (int k = 0; k < 15; k++) {
            float e = expf(slog[q][k] - mx);
            slog[q][k] = e;
            sum += e;
        }
        float inv = 1.0f / sum;
#pragma unroll
        for (int k = 0; k < 15; k++) slog[q][k] *= inv;
    }
    __syncthreads();
    for (int idx = tid; idx < 960; idx += 256) {
        int q = idx >> 6, d = idx & 63;
        float s = 0.f;
#pragma unroll
        for (int k = 0; k < 15; k++) s += slog[q][k] * sm[2][k][d];
        out[((size_t)b * 15 + q) * 1024 + h * 64 + d] = __float2half(s);
    }
}

// ---------------------------------------------------------------------------
extern "C" void kernel_launch(void* const* d_in, const int* in_sizes, int n_in,
                              void* d_out, int out_size) {
    const float* joint  = (const float*)d_in[0];
    const float* rel    = (const float*)d_in[1];
    const float* W_Jqkv = (const float*)d_in[2];
    const float* W_Iqk  = (const float*)d_in[3];
    const float* W_Iconv= (const float*)d_in[4];
    const float* W_proj = (const float*)d_in[5];
    const float* b_proj = (const float*)d_in[6];
    const float* g1 = (const float*)d_in[7];
    const float* b1 = (const float*)d_in[8];
    const float* g2 = (const float*)d_in[9];
    const float* b2 = (const float*)d_in[10];
    const float* gj = (const float*)d_in[11];
    const float* bj = (const float*)d_in[12];
    const float* W_fc1 = (const float*)d_in[13];
    const float* b_fc1 = (const float*)d_in[14];
    const float* W_fc2 = (const float*)d_in[15];
    const float* b_fc2 = (const float*)d_in[16];
    float* out = (float*)d_out;

    f16 *xj, *xi, *Jqkv, *Iqk, *attno, *ln2, *hid;
    f16 *wJ, *wI, *wP, *w1, *w2;
    float *jointb, *wlin;
    cudaGetSymbolAddress((void**)&xj, g_xj);
    cudaGetSymbolAddress((void**)&xi, g_xi);
    cudaGetSymbolAddress((void**)&Jqkv, g_Jqkv);
    cudaGetSymbolAddress((void**)&Iqk, g_Iqk);
    cudaGetSymbolAddress((void**)&attno, g_attno);
    cudaGetSymbolAddress((void**)&ln2, g_ln2);
    cudaGetSymbolAddress((void**)&hid, g_hid);
    cudaGetSymbolAddress((void**)&jointb, g_joint);
    cudaGetSymbolAddress((void**)&wlin, g_wlin);
    cudaGetSymbolAddress((void**)&wJ, g_wJ);
    cudaGetSymbolAddress((void**)&wI, g_wI);
    cudaGetSymbolAddress((void**)&wP, g_wP);
    cudaGetSymbolAddress((void**)&w1, g_w1);
    cudaGetSymbolAddress((void**)&w2, g_w2);

    cudaFuncSetAttribute(gemm_hmma<32, 0, f16>,
                         cudaFuncAttributeMaxDynamicSharedMemorySize, GSMEM_BYTES);
    cudaFuncSetAttribute(gemm_hmma<32, 1, float>,
                         cudaFuncAttributeMaxDynamicSharedMemorySize, GSMEM_BYTES);
    cudaFuncSetAttribute(gemm_hmma<32, 2, f16>,
                         cudaFuncAttributeMaxDynamicSharedMemorySize, GSMEM_BYTES);
    cudaFuncSetAttribute(gemm_hmma<16, 1, float>,
                         cudaFuncAttributeMaxDynamicSharedMemorySize, GSMEM_BYTES);

    // weight prep
    wlin_kernel<<<960, 256>>>(W_Iqk, W_Iconv, wlin);
    pack_wI_kernel<<<9216, 256>>>(W_Iqk, wlin, wI);
    f2h_kernel<<<3072, 256>>>(W_Jqkv, wJ, 1024 * 3072);
    f2h_kernel<<<1024, 256>>>(W_proj, wP, 1024 * 1024);
    f2h_kernel<<<512, 256>>>(W_fc1, w1, 1024 * 512);
    f2h_kernel<<<512, 256>>>(W_fc2, w2, 512 * 1024);

    // 1. dual LN
    ln_kernel<<<M_ROWS, 256>>>(joint, g1, b1, xj);
    ln_kernel<<<M_ROWS, 256>>>(rel, g2, b2, xi);
    // 2/3. projections
    gemm_hmma<32, 0, f16><<<dim3(24, 240), 256, GSMEM_BYTES>>>(
        xj, wJ, nullptr, nullptr, Jqkv, 3072);
    gemm_hmma<32, 0, f16><<<dim3(18, 240), 256, GSMEM_BYTES>>>(
        xi, wI, nullptr, nullptr, Iqk, 2304);
    // 4. attention
    attn_kernel<<<dim3(2048, 16), 256>>>(Jqkv, Iqk, attno);
    // 5. proj + bias + residual -> fp32 joint
    gemm_hmma<32, 1, float><<<dim3(8, 240), 256, GSMEM_BYTES>>>(
        attno, wP, b_proj, joint, jointb, 1024);
    // 6. MLP
    ln_kernel<<<M_ROWS, 256>>>(jointb, gj, bj, ln2);
    gemm_hmma<32, 2, f16><<<dim3(4, 240), 256, GSMEM_BYTES>>>(
        ln2, w1, b_fc1, nullptr, hid, 512);
    gemm_hmma<16, 1, float><<<dim3(8, 240), 256, GSMEM_BYTES>>>(
        hid, w2, b_fc2, jointb, out, 1024);
}

// round 11
// speedup vs baseline: 1.0232x; 1.0232x over previous
#include <cuda_runtime.h>
#include <cuda_fp16.h>
#include <math.h>
#include <stdint.h>

// ---------------------------------------------------------------------------
// Fused transformer block: B=2048, N=15, C=1024, H=16, HS=64
// Round 11: R8 config (fp16 HMMA 128x128/64x32, k64 2-stage, 2 CTAs/SM,
//           W_Iconv folded) + merged QKV launch (wave-tail) + merged f2h
//           (launch order puts QKV GEMM at ncu capture slot #5).
// ---------------------------------------------------------------------------

#define M_ROWS 30720
using f16 = __half;

__device__ f16   g_xj[(size_t)M_ROWS * 1024];
__device__ f16   g_xi[(size_t)M_ROWS * 1024];
__device__ f16   g_Jqkv[(size_t)M_ROWS * 3072];
__device__ f16   g_Iqk[(size_t)M_ROWS * 2304];
__device__ f16   g_attno[(size_t)M_ROWS * 1024];
__device__ f16   g_ln2[(size_t)M_ROWS * 1024];
__device__ f16   g_hid[(size_t)M_ROWS * 512];
__device__ float g_joint[(size_t)M_ROWS * 1024];
__device__ float g_wlin[1024 * 240];
// fp16 weights (native [K,N])
__device__ f16 g_wJ[1024 * 3072];
__device__ f16 g_wI[1024 * 2304];
__device__ f16 g_wP[1024 * 1024];
__device__ f16 g_w1[1024 * 512];
__device__ f16 g_w2[512 * 1024];

// ---------------------------------------------------------------------------
__device__ __forceinline__ uint32_t smem_u32(const void* p) {
    uint32_t a;
    asm("{ .reg .u64 t; cvta.to.shared.u64 t, %1; cvt.u32.u64 %0, t; }"
        : "=r"(a) : "l"(p));
    return a;
}
__device__ __forceinline__ void cp16s(uint32_t saddr, const void* g) {
    asm volatile("cp.async.cg.shared.global [%0], [%1], 16;\n" ::"r"(saddr),
                 "l"(g));
}
__device__ __forceinline__ void cp_commit() {
    asm volatile("cp.async.commit_group;\n");
}
template <int NN>
__device__ __forceinline__ void cp_wait() {
    asm volatile("cp.async.wait_group %0;\n" ::"n"(NN));
}
__device__ __forceinline__ float gelu_exact(float x) {
    return 0.5f * x * (1.0f + erff(x * 0.70710678118654752f));
}

// ---------------------------------------------------------------------------
// W_lin[c][h*15+j] = sum_d W_Iqk[c][2048+h*64+d] * W_Iconv[d][j]
// ---------------------------------------------------------------------------
__global__ __launch_bounds__(256) void wlin_kernel(
    const float* __restrict__ W_Iqk, const float* __restrict__ W_Iconv,
    float* __restrict__ out) {
    int idx = blockIdx.x * 256 + threadIdx.x;  // 1024*240
    int c = idx / 240, r = idx % 240;
    int h = r / 15, j = r % 15;
    const float* wv = W_Iqk + (size_t)c * 3072 + 2048 + h * 64;
    float s = 0.f;
#pragma unroll 8
    for (int d = 0; d < 64; d++) s += wv[d] * W_Iconv[d * 15 + j];
    out[idx] = s;
}

// pack Iqk weight: cols [0,2048) from W_Iqk, [2048,2288) = wlin, pad 0
__global__ __launch_bounds__(256) void pack_wI_kernel(
    const float* __restrict__ W_Iqk, const float* __restrict__ wlin,
    f16* __restrict__ out) {
    int idx = blockIdx.x * 256 + threadIdx.x;  // 1024*2304
    int k = idx / 2304, n = idx % 2304;
    float v = (n < 2048) ? W_Iqk[(size_t)k * 3072 + n]
                         : ((n < 2288) ? wlin[k * 240 + (n - 2048)] : 0.f);
    out[idx] = __float2half(v);
}

// all four fp32->fp16 weight conversions in one launch
// segments (in float4 units): wJ 786432 | wP 262144 | w1 131072 | w2 131072
__global__ __launch_bounds__(256) void f2h_all_kernel(
    const float* __restrict__ iJ, const float* __restrict__ iP,
    const float* __restrict__ i1, const float* __restrict__ i2,
    f16* __restrict__ oJ, f16* __restrict__ oP, f16* __restrict__ o1,
    f16* __restrict__ o2) {
    int t = blockIdx.x * 256 + threadIdx.x;  // < 1310720
    const float* in;
    f16* out;
    int i;
    if (t < 786432) { in = iJ; out = oJ; i = t; }
    else if (t < 1048576) { in = iP; out = oP; i = t - 786432; }
    else if (t < 1179648) { in = i1; out = o1; i = t - 1048576; }
    else { in = i2; out = o2; i = t - 1179648; }
    float4 v = *reinterpret_cast<const float4*>(in + (size_t)i * 4);
    *reinterpret_cast<__half2*>(out + (size_t)i * 4) =
        __floats2half2_rn(v.x, v.y);
    *reinterpret_cast<__half2*>(out + (size_t)i * 4 + 2) =
        __floats2half2_rn(v.z, v.w);
}

// ---------------------------------------------------------------------------
// LayerNorm (fp32 in, fp16 out)
// ---------------------------------------------------------------------------
__global__ __launch_bounds__(256) void ln_kernel(
    const float* __restrict__ x, const float* __restrict__ g,
    const float* __restrict__ b, f16* __restrict__ out) {
    int row = blockIdx.x;
    const float4* xr = reinterpret_cast<const float4*>(x + (size_t)row * 1024);
    float4 v = xr[threadIdx.x];
    float s = v.x + v.y + v.z + v.w;
    float sq = v.x * v.x + v.y * v.y + v.z * v.z + v.w * v.w;
#pragma unroll
    for (int o = 16; o > 0; o >>= 1) {
        s += __shfl_xor_sync(0xffffffffu, s, o);
        sq += __shfl_xor_sync(0xffffffffu, sq, o);
    }
    __shared__ float ss[8], ssq[8];
    int w = threadIdx.x >> 5;
    if ((threadIdx.x & 31) == 0) { ss[w] = s; ssq[w] = sq; }
    __syncthreads();
    float ts = 0.f, tq = 0.f;
#pragma unroll
    for (int i = 0; i < 8; i++) { ts += ss[i]; tq += ssq[i]; }
    float mean = ts * (1.0f / 1024.0f);
    float var = tq * (1.0f / 1024.0f) - mean * mean;
    float rstd = rsqrtf(var + 1e-5f);
    int c = threadIdx.x * 4;
    float4 gg = *reinterpret_cast<const float4*>(g + c);
    float4 bb = *reinterpret_cast<const float4*>(b + c);
    float o0 = (v.x - mean) * rstd * gg.x + bb.x;
    float o1 = (v.y - mean) * rstd * gg.y + bb.y;
    float o2 = (v.z - mean) * rstd * gg.z + bb.z;
    float o3 = (v.w - mean) * rstd * gg.w + bb.w;
    f16* orow = out + (size_t)row * 1024 + c;
    *reinterpret_cast<__half2*>(orow) = __floats2half2_rn(o0, o1);
    *reinterpret_cast<__half2*>(orow + 2) = __floats2half2_rn(o2, o3);
}

// ---------------------------------------------------------------------------
// fp16 HMMA GEMM body: C[128 tile] = A[M,K] @ B[K,N] (+epilogue)
// CTA 128x128x64, 8 warps (2x4), warp 64x32 m16n8k16, 2-stage cp.async.
// SMEM stage: A 128x144B (18432), B 64x272B (17408); STAGE=35840; 2 stages.
// EPI: 0 = fp16 out; 1 = +bias+residual fp32 out; 2 = +bias, GELU, fp16 out
// ---------------------------------------------------------------------------
#define STAGE_B 35840
#define GSMEM_BYTES (2 * STAGE_B)

template <int KT, int EPI, typename OT>
__device__ __forceinline__ void gemm_body(
    const f16* __restrict__ A, const f16* __restrict__ Bw,
    const float* __restrict__ bias, const float* __restrict__ res,
    OT* __restrict__ Cout, int N, int bm, int bn, uint32_t sb) {
    const int K = KT * 64;
    int tid = threadIdx.x, lane = tid & 31, wid = tid >> 5;
    int wm = (wid >> 2) * 64, wn = (wid & 3) * 32;
    int g = lane >> 2, tg = lane & 3;

    float acc[4][4][4];
#pragma unroll
    for (int a = 0; a < 4; a++)
#pragma unroll
        for (int b2 = 0; b2 < 4; b2++)
#pragma unroll
            for (int c = 0; c < 4; c++) acc[a][b2][c] = 0.f;

    auto load_stage = [&](int s, int t) {
        uint32_t ab = sb + s * STAGE_B;
        uint32_t bb2 = ab + 18432;
#pragma unroll
        for (int i = 0; i < 4; i++) {
            int c = tid + i * 256;
            int r = c >> 3, ch = c & 7;
            cp16s(ab + r * 144 + ch * 16,
                  A + (size_t)(bm + r) * K + t * 64 + ch * 8);
        }
#pragma unroll
        for (int i = 0; i < 4; i++) {
            int c = tid + i * 256;
            int r = c >> 4, ch = c & 15;
            cp16s(bb2 + r * 272 + ch * 16,
                  Bw + (size_t)(t * 64 + r) * N + bn + ch * 8);
        }
    };

    load_stage(0, 0);
    cp_commit();

#pragma unroll 1
    for (int t = 0; t < KT; ++t) {
        if (t + 1 < KT) {
            load_stage((t + 1) & 1, t + 1);
            cp_commit();
            cp_wait<1>();
        } else {
            cp_wait<0>();
        }
        __syncthreads();
        uint32_t ab = sb + (t & 1) * STAGE_B;
        uint32_t bb2 = ab + 18432;
#pragma unroll
        for (int kk = 0; kk < 64; kk += 16) {
            unsigned af[4][4], bfr[2][4];
#pragma unroll
            for (int mt = 0; mt < 4; mt++) {
                uint32_t addr = ab + (wm + mt * 16 + (lane & 15)) * 144 +
                                (kk + (lane >> 4) * 8) * 2;
                asm volatile(
                    "ldmatrix.sync.aligned.m8n8.x4.shared.b16 {%0,%1,%2,%3},[%4];"
                    : "=r"(af[mt][0]), "=r"(af[mt][1]), "=r"(af[mt][2]),
                      "=r"(af[mt][3])
                    : "r"(addr));
            }
#pragma unroll
            for (int hh = 0; hh < 2; hh++) {
                uint32_t addr = bb2 + (kk + (lane & 15)) * 272 +
                                (wn + hh * 16 + (lane >> 4) * 8) * 2;
                asm volatile(
                    "ldmatrix.sync.aligned.m8n8.x4.trans.shared.b16 "
                    "{%0,%1,%2,%3},[%4];"
                    : "=r"(bfr[hh][0]), "=r"(bfr[hh][1]), "=r"(bfr[hh][2]),
                      "=r"(bfr[hh][3])
                    : "r"(addr));
            }
#pragma unroll
            for (int mt = 0; mt < 4; mt++)
#pragma unroll
                for (int nt = 0; nt < 4; nt++) {
                    unsigned b0 = bfr[nt >> 1][(nt & 1) * 2];
                    unsigned b1 = bfr[nt >> 1][(nt & 1) * 2 + 1];
                    asm volatile(
                        "mma.sync.aligned.m16n8k16.row.col.f32.f16.f16.f32 "
                        "{%0,%1,%2,%3},{%4,%5,%6,%7},{%8,%9},{%0,%1,%2,%3};"
                        : "+f"(acc[mt][nt][0]), "+f"(acc[mt][nt][1]),
                          "+f"(acc[mt][nt][2]), "+f"(acc[mt][nt][3])
                        : "r"(af[mt][0]), "r"(af[mt][1]), "r"(af[mt][2]),
                          "r"(af[mt][3]), "r"(b0), "r"(b1));
                }
        }
        __syncthreads();
    }

    // epilogue
#pragma unroll
    for (int mt = 0; mt < 4; mt++) {
        int row = bm + wm + mt * 16 + g;
#pragma unroll
        for (int nt = 0; nt < 4; nt++) {
            int col = bn + wn + nt * 8 + 2 * tg;
            size_t i0 = (size_t)row * N + col;
            size_t i1 = i0 + (size_t)8 * N;
            float c0 = acc[mt][nt][0], c1 = acc[mt][nt][1];
            float c2 = acc[mt][nt][2], c3 = acc[mt][nt][3];
            if (EPI == 1) {
                float2 bb = *reinterpret_cast<const float2*>(bias + col);
                float2 r0 = *reinterpret_cast<const float2*>(res + i0);
                float2 r1 = *reinterpret_cast<const float2*>(res + i1);
                c0 += bb.x + r0.x; c1 += bb.y + r0.y;
                c2 += bb.x + r1.x; c3 += bb.y + r1.y;
            } else if (EPI == 2) {
                float2 bb = *reinterpret_cast<const float2*>(bias + col);
                c0 = gelu_exact(c0 + bb.x); c1 = gelu_exact(c1 + bb.y);
                c2 = gelu_exact(c2 + bb.x); c3 = gelu_exact(c3 + bb.y);
            }
            if (sizeof(OT) == 4) {
                *reinterpret_cast<float2*>((float*)Cout + i0) = make_float2(c0, c1);
                *reinterpret_cast<float2*>((float*)Cout + i1) = make_float2(c2, c3);
            } else {
                *reinterpret_cast<__half2*>((f16*)Cout + i0) =
                    __floats2half2_rn(c0, c1);
                *reinterpret_cast<__half2*>((f16*)Cout + i1) =
                    __floats2half2_rn(c2, c3);
            }
        }
    }
}

template <int KT, int EPI, typename OT>
__global__ __launch_bounds__(256, 2) void gemm_hmma(
    const f16* __restrict__ A, const f16* __restrict__ Bw,
    const float* __restrict__ bias, const float* __restrict__ res,
    OT* __restrict__ Cout, int N) {
    extern __shared__ __align__(128) char smem[];
    gemm_body<KT, EPI, OT>(A, Bw, bias, res, Cout, N,
                           blockIdx.y * 128, blockIdx.x * 128, smem_u32(smem));
}

// merged QKV: linear grid; [0,5760) = J GEMM (24 n-blocks), rest = I (18)
__global__ __launch_bounds__(256, 2) void qkv_kernel(
    const f16* __restrict__ xj, const f16* __restrict__ wJ,
    f16* __restrict__ Jqkv, const f16* __restrict__ xi,
    const f16* __restrict__ wI, f16* __restrict__ Iqk) {
    extern __shared__ __align__(128) char smem[];
    int id = blockIdx.x;
    if (id < 5760) {
        gemm_body<16, 0, f16>(xj, wJ, nullptr, nullptr, Jqkv, 3072,
                              (id / 24) * 128, (id % 24) * 128, smem_u32(smem));
    } else {
        id -= 5760;
        gemm_body<16, 0, f16>(xi, wI, nullptr, nullptr, Iqk, 2304,
                              (id / 18) * 128, (id % 18) * 128, smem_u32(smem));
    }
}

// ---------------------------------------------------------------------------
// Attention: block per (b,h). logits = (JqJk + IqIk + lin)*0.125; out = P@Jv
// ---------------------------------------------------------------------------
__global__ __launch_bounds__(256) void attn_kernel(
    const f16* __restrict__ Jqkv, const f16* __restrict__ Iqk,
    f16* __restrict__ out) {
    int b = blockIdx.x, h = blockIdx.y;
    __shared__ float sm[5][15][64];  // Jq Jk Jv Iq Ik
    __shared__ float slin[15][15];
    __shared__ float slog[15][16];
    int tid = threadIdx.x;
    size_t baseJ = ((size_t)b * 15) * 3072 + h * 64;
    size_t baseI = ((size_t)b * 15) * 2304 + h * 64;

    for (int idx = tid; idx < 600; idx += 256) {
        int mat = idx / 120;
        int rem = idx % 120;
        int n = rem >> 3;
        int c8 = rem & 7;
        const f16* src;
        if (mat < 3) src = Jqkv + baseJ + (size_t)n * 3072 + mat * 1024;
        else         src = Iqk + baseI + (size_t)n * 2304 + (mat - 3) * 1024;
        const __half2* p = reinterpret_cast<const __half2*>(src + c8 * 8);
        float* d = &sm[mat][n][c8 * 8];
#pragma unroll
        for (int j = 0; j < 4; j++) {
            float2 f = __half22float2(p[j]);
            d[2 * j] = f.x;
            d[2 * j + 1] = f.y;
        }
    }
    if (tid < 225) {
        int q = tid / 15, k = tid % 15;
        slin[q][k] = __half2float(
            Iqk[((size_t)b * 15 + q) * 2304 + 2048 + h * 15 + k]);
    }
    __syncthreads();

    if (tid < 225) {
        int q = tid / 15, k = tid % 15;
        float s = slin[q][k];
#pragma unroll 8
        for (int d = 0; d < 64; d++) {
            s += sm[0][q][d] * sm[1][k][d];
            s += sm[3][q][d] * sm[4][k][d];
        }
        slog[q][k] = s * 0.125f;
    }
    __syncthreads();
    if (tid < 15) {
        int q = tid;
        float mx = -1e30f;
#pragma unroll
        for (int k = 0; k < 15; k++) mx = fmaxf(mx, slog[q][k]);
        float sum = 0.f;
#pragma unroll
        for (int k = 0; k < 15; k++) {
            float e = expf(slog[q][k] - mx);
            slog[q][k] = e;
            sum += e;
        }
        float inv = 1.0f / sum;
#pragma unroll
        for (int k = 0; k < 15; k++) slog[q][k] *= inv;
    }
    __syncthreads();
    for (int idx = tid; idx < 960; idx += 256) {
        int q = idx >> 6, d = idx & 63;
        float s = 0.f;
#pragma unroll
        for (int k = 0; k < 15; k++) s += slog[q][k] * sm[2][k][d];
        out[((size_t)b * 15 + q) * 1024 + h * 64 + d] = __float2half(s);
    }
}

// ---------------------------------------------------------------------------
extern "C" void kernel_launch(void* const* d_in, const int* in_sizes, int n_in,
                              void* d_out, int out_size) {
    const float* joint  = (const float*)d_in[0];
    const float* rel    = (const float*)d_in[1];
    const float* W_Jqkv = (const float*)d_in[2];
    const float* W_Iqk  = (const float*)d_in[3];
    const float* W_Iconv= (const float*)d_in[4];
    const float* W_proj = (const float*)d_in[5];
    const float* b_proj = (const float*)d_in[6];
    const float* g1 = (const float*)d_in[7];
    const float* b1 = (const float*)d_in[8];
    const float* g2 = (const float*)d_in[9];
    const float* b2 = (const float*)d_in[10];
    const float* gj = (const float*)d_in[11];
    const float* bj = (const float*)d_in[12];
    const float* W_fc1 = (const float*)d_in[13];
    const float* b_fc1 = (const float*)d_in[14];
    const float* W_fc2 = (const float*)d_in[15];
    const float* b_fc2 = (const float*)d_in[16];
    float* out = (float*)d_out;

    f16 *xj, *xi, *Jqkv, *Iqk, *attno, *ln2, *hid;
    f16 *wJ, *wI, *wP, *w1, *w2;
    float *jointb, *wlin;
    cudaGetSymbolAddress((void**)&xj, g_xj);
    cudaGetSymbolAddress((void**)&xi, g_xi);
    cudaGetSymbolAddress((void**)&Jqkv, g_Jqkv);
    cudaGetSymbolAddress((void**)&Iqk, g_Iqk);
    cudaGetSymbolAddress((void**)&attno, g_attno);
    cudaGetSymbolAddress((void**)&ln2, g_ln2);
    cudaGetSymbolAddress((void**)&hid, g_hid);
    cudaGetSymbolAddress((void**)&jointb, g_joint);
    cudaGetSymbolAddress((void**)&wlin, g_wlin);
    cudaGetSymbolAddress((void**)&wJ, g_wJ);
    cudaGetSymbolAddress((void**)&wI, g_wI);
    cudaGetSymbolAddress((void**)&wP, g_wP);
    cudaGetSymbolAddress((void**)&w1, g_w1);
    cudaGetSymbolAddress((void**)&w2, g_w2);

    cudaFuncSetAttribute(qkv_kernel,
                         cudaFuncAttributeMaxDynamicSharedMemorySize, GSMEM_BYTES);
    cudaFuncSetAttribute(gemm_hmma<16, 1, float>,
                         cudaFuncAttributeMaxDynamicSharedMemorySize, GSMEM_BYTES);
    cudaFuncSetAttribute(gemm_hmma<16, 2, f16>,
                         cudaFuncAttributeMaxDynamicSharedMemorySize, GSMEM_BYTES);
    cudaFuncSetAttribute(gemm_hmma<8, 1, float>,
                         cudaFuncAttributeMaxDynamicSharedMemorySize, GSMEM_BYTES);

    // weight prep (launches 0..2)
    wlin_kernel<<<960, 256>>>(W_Iqk, W_Iconv, wlin);
    pack_wI_kernel<<<9216, 256>>>(W_Iqk, wlin, wI);
    f2h_all_kernel<<<5120, 256>>>(W_Jqkv, W_proj, W_fc1, W_fc2, wJ, wP, w1, w2);

    // 1. dual LN (launches 3,4)
    ln_kernel<<<M_ROWS, 256>>>(joint, g1, b1, xj);
    ln_kernel<<<M_ROWS, 256>>>(rel, g2, b2, xi);
    // 2/3. merged QKV projections (launch 5 — ncu capture slot)
    qkv_kernel<<<10080, 256, GSMEM_BYTES>>>(xj, wJ, Jqkv, xi, wI, Iqk);
    // 4. attention
    attn_kernel<<<dim3(2048, 16), 256>>>(Jqkv, Iqk, attno);
    // 5. proj + bias + residual -> fp32 joint
    gemm_hmma<16, 1, float><<<dim3(8, 240), 256, GSMEM_BYTES>>>(
        attno, wP, b_proj, joint, jointb, 1024);
    // 6. MLP
    ln_kernel<<<M_ROWS, 256>>>(jointb, gj, bj, ln2);
    gemm_hmma<16, 2, f16><<<dim3(4, 240), 256, GSMEM_BYTES>>>(
        ln2, w1, b_fc1, nullptr, hid, 512);
    gemm_hmma<8, 1, float><<<dim3(8, 240), 256, GSMEM_BYTES>>>(
        hid, w2, b_fc2, jointb, out, 1024);
}